// round 13
// baseline (speedup 1.0000x reference)
#include <cuda_runtime.h>
#include <math.h>

#define F 256
#define NB 1024            // row-chunks: B=65536 -> exactly 64 rows per chunk

// Stage-1 partials, transposed: [F][NB] float4 = 4 MB
__device__ float4 g_part[F * NB];
__device__ double g_bits[F];

typedef unsigned long long u64t;

__device__ __forceinline__ float fast_lg2(float a) {
    float r; asm("lg2.approx.f32 %0, %1;" : "=f"(r) : "f"(a)); return r;
}
__device__ __forceinline__ float fast_ex2(float a) {
    float r; asm("ex2.approx.f32 %0, %1;" : "=f"(r) : "f"(a)); return r;
}
// ---- packed f32x2 (Blackwell FADD2/FMUL2/FFMA2; PTX-only) ----
__device__ __forceinline__ u64t pk2(float lo, float hi) {
    u64t r; asm("mov.b64 %0, {%1, %2};" : "=l"(r) : "f"(lo), "f"(hi)); return r;
}
__device__ __forceinline__ void upk2(u64t v, float& lo, float& hi) {
    asm("mov.b64 {%0, %1}, %2;" : "=f"(lo), "=f"(hi) : "l"(v));
}
__device__ __forceinline__ u64t pkadd(u64t a, u64t b) {
    u64t r; asm("add.rn.f32x2 %0, %1, %2;" : "=l"(r) : "l"(a), "l"(b)); return r;
}
__device__ __forceinline__ u64t pkmul(u64t a, u64t b) {
    u64t r; asm("mul.rn.f32x2 %0, %1, %2;" : "=l"(r) : "l"(a), "l"(b)); return r;
}
__device__ __forceinline__ u64t pkfma(u64t a, u64t b, u64t c) {
    u64t r; asm("fma.rn.f32x2 %0, %1, %2, %3;" : "=l"(r) : "l"(a), "l"(b), "l"(c)); return r;
}

// Vector pass1: grid NB x 256 threads.
//   p   = tid & 127 : feature pair -> features {2p, 2p+1} (one float2 load)
//   par = tid >> 7  : row parity   -> rows chunk*64 + (2r+par), r=0..31
// Accumulators are packed f32x2; halves = the two features. Parity halves are
// combined through smem at the end so the partial layout stays [F][NB].
template<int ITER>
__global__ void __launch_bounds__(256) mdl_pass1_v(
    const float* __restrict__ res,
    const float* __restrict__ lambda1,
    const float* __restrict__ lambda2)
{
    const int p   = threadIdx.x & 127;
    const int par = threadIdx.x >> 7;
    const int f0  = p * 2;

    float lamP[2], lamN[2], rlamP[2], nrlamN[2], loBv[2], hiBv[2];
#pragma unroll
    for (int k = 0; k < 2; ++k) {
        const float l1 = lambda1[f0 + k];
        const float l2 = lambda2[f0 + k];
        float lp = (fabsf(l1) < 1e-8f) ? 1e-8f : l1;
        float ln = 2.0f - l2;
        if (fabsf(ln) < 1e-8f) ln = 1e-8f;
        lamP[k] = lp;           lamN[k]   = ln;
        rlamP[k] = 1.0f / lp;   nrlamN[k] = -1.0f / ln;
        hiBv[k] = (fabsf(l1) <= 1.9f) ? 1000.0f : -0.0f;
        loBv[k] = (fabsf(l2) <= 1.9f) ? -0.99f  :  0.0f;
    }
    const u64t NEG1 = pk2(-1.0f, -1.0f);

    const float2* pp = reinterpret_cast<const float2*>(
        res + ((size_t)blockIdx.x * (2 * ITER) + par) * F) + p;

    u64t cnt2 = 0, sy2p = 0, syy2 = 0, slj2 = 0;   // 0 == pk2(0,0)

#pragma unroll 4
    for (int r = 0; r < ITER; ++r) {
        const float2 v = __ldcs(pp + r * F);       // 2 rows stride = F float2s
        float t2h[2], u2h[2], eeh[2], rlh[2], mh[2];
        const float xs[2] = {v.x, v.y};
#pragma unroll
        for (int k = 0; k < 2; ++k) {
            const float x = xs[k];
            const bool pos = (x >= 0.0f);
            const float a = 1.0f + fabsf(fmaxf(x, -0.989f));
            t2h[k] = fast_lg2(a);
            u2h[k] = (pos ? lamP[k] : lamN[k]) * t2h[k];
            eeh[k] = fast_ex2(u2h[k]);
            rlh[k] = pos ? rlamP[k] : nrlamN[k];
            mh[k]  = ((x > loBv[k]) && (x <= hiBv[k])) ? 1.0f : 0.0f;
        }
        const u64t t2 = pk2(t2h[0], t2h[1]);
        const u64t u2 = pk2(u2h[0], u2h[1]);
        const u64t ee = pk2(eeh[0], eeh[1]);
        const u64t rl = pk2(rlh[0], rlh[1]);
        const u64t m  = pk2(mh[0],  mh[1]);

        const u64t e  = pkfma(ee, pk2(1.0f, 1.0f), NEG1);  // ee - 1
        const u64t y  = pkmul(e, rl);
        const u64t my = pkmul(m, y);
        const u64t d  = pkfma(t2, NEG1, u2);               // u2 - t2
        cnt2 = pkadd(cnt2, m);
        sy2p = pkadd(sy2p, my);
        syy2 = pkfma(my, y, syy2);
        slj2 = pkfma(m, d, slj2);
    }

    // combine parity halves through smem; halves of each packed acc are the
    // two features, so unpack to per-feature float4 partials.
    __shared__ float4 s_acc[2][128][2];
    float c0,c1, s0,s1, q0,q1, j0,j1;
    upk2(cnt2, c0,c1); upk2(sy2p, s0,s1); upk2(syy2, q0,q1); upk2(slj2, j0,j1);
    s_acc[par][p][0] = make_float4(c0, s0, q0, j0);
    s_acc[par][p][1] = make_float4(c1, s1, q1, j1);
    __syncthreads();
    if (par == 0) {
#pragma unroll
        for (int k = 0; k < 2; ++k) {
            const float4 a = s_acc[0][p][k];
            const float4 b = s_acc[1][p][k];
            g_part[(f0 + k) * NB + blockIdx.x] =
                make_float4(a.x + b.x, a.y + b.y, a.z + b.z, a.w + b.w);
        }
    }
}

// Generic scalar fallback (arbitrary B, assumes B % NB == 0)
__global__ void __launch_bounds__(256) mdl_pass1_s(
    const float* __restrict__ res,
    const float* __restrict__ lambda1,
    const float* __restrict__ lambda2,
    int rows)
{
    const int f = threadIdx.x;
    const float l1 = lambda1[f];
    const float l2 = lambda2[f];
    float lp = (fabsf(l1) < 1e-8f) ? 1e-8f : l1;
    float ln = 2.0f - l2;
    if (fabsf(ln) < 1e-8f) ln = 1e-8f;
    const float rlp  =  1.0f / lp;
    const float nrln = -1.0f / ln;
    const float hiB = (fabsf(l1) <= 1.9f) ? 1000.0f : -0.0f;
    const float loB = (fabsf(l2) <= 1.9f) ? -0.99f  :  0.0f;

    const float* pr = res + (size_t)blockIdx.x * rows * F + f;
    float cnt = 0, sy = 0, sy2 = 0, slj2 = 0;
#pragma unroll 8
    for (int r = 0; r < rows; ++r) {
        const float x = __ldcs(pr + r * F);
        const bool pos = (x >= 0.0f);
        const float a  = 1.0f + fabsf(fmaxf(x, -0.989f));
        const float t2 = fast_lg2(a);
        const float u2 = (pos ? lp : ln) * t2;
        const float y  = (fast_ex2(u2) - 1.0f) * (pos ? rlp : nrln);
        if ((x > loB) && (x <= hiB)) {
            cnt += 1.0f; sy += y; sy2 = fmaf(y, y, sy2); slj2 += (u2 - t2);
        }
    }
    g_part[f * NB + blockIdx.x] = make_float4(cnt, sy, sy2, slj2);
}

// 256 blocks (one feature each) x 256 threads: warp w reduces entries
// [w*128, (w+1)*128); shuffle + smem combine; thread 0 does the double math.
__global__ __launch_bounds__(256) void mdl_pass2a(
    const float* __restrict__ resolutions, int B)
{
    const int gf   = blockIdx.x;
    const int w    = threadIdx.x >> 5;
    const int lane = threadIdx.x & 31;

    const float4* b0 = g_part + (size_t)gf * NB;
    double cnt = 0.0, sy = 0.0, sy2 = 0.0, slj = 0.0;
#pragma unroll 4
    for (int b = w * (NB / 8) + lane; b < (w + 1) * (NB / 8); b += 32) {
        const float4 v = b0[b];
        cnt += (double)v.x; sy += (double)v.y;
        sy2 += (double)v.z; slj += (double)v.w;
    }
#pragma unroll
    for (int o = 16; o > 0; o >>= 1) {
        cnt += __shfl_down_sync(0xffffffffu, cnt, o);
        sy  += __shfl_down_sync(0xffffffffu, sy,  o);
        sy2 += __shfl_down_sync(0xffffffffu, sy2, o);
        slj += __shfl_down_sync(0xffffffffu, slj, o);
    }

    __shared__ double sh[8][4];
    if (lane == 0) { sh[w][0] = cnt; sh[w][1] = sy; sh[w][2] = sy2; sh[w][3] = slj; }
    __syncthreads();

    if (threadIdx.x == 0) {
        cnt = 0; sy = 0; sy2 = 0; slj = 0;
#pragma unroll
        for (int i = 0; i < 8; ++i) {
            cnt += sh[i][0]; sy += sh[i][1]; sy2 += sh[i][2]; slj += sh[i][3];
        }

        const double LN2 = 0.6931471805599453;
        const double LOG2_2PIE = 2.0470955851806783;

        const double Bd    = (double)B;
        const double nf    = cnt;
        const double nexc  = Bd - nf;
        const double denom = fmax(nf, 1.0);
        const double mean  = sy / denom;
        double var = (sy2 - 2.0 * mean * sy + mean * mean * nf) / denom;
        var = fmax(var, 1e-12);

        const double diff_bits = (nf > 1.0) ? nf * (LOG2_2PIE + 0.5 * log2(var)) : 0.0;
        const double jac_bits  = slj;        // accumulated in log2 units
        const double rres      = (double)resolutions[gf];
        const double exc_bits  = (nexc > 0.0) ? nexc * (-log2(rres)) : 0.0;
        const double log_binom = lgamma(Bd + 1.0) - lgamma(nexc + 1.0)
                               - lgamma(Bd - nexc + 1.0);
        const double part_bits = (nexc > 0.0 && nexc < Bd) ? (log_binom / LN2) : 0.0;
        const double lambda_bits = 2.0 * (log(100.0) / LN2);

        g_bits[gf] = diff_bits + jac_bits + exc_bits + part_bits + lambda_bits;
    }
}

__global__ __launch_bounds__(256) void mdl_pass2b(float* __restrict__ out)
{
    const int f = threadIdx.x;
    __shared__ double sh[F];
    sh[f] = g_bits[f];
    __syncthreads();
#pragma unroll
    for (int s = 128; s > 0; s >>= 1) {
        if (f < s) sh[f] += sh[f + s];
        __syncthreads();
    }
    if (f == 0) out[0] = (float)sh[0];
}

extern "C" void kernel_launch(void* const* d_in, const int* in_sizes, int n_in,
                              void* d_out, int out_size)
{
    const float* residuals   = (const float*)d_in[0];
    const float* lambda1     = (const float*)d_in[1];
    const float* lambda2     = (const float*)d_in[2];
    const float* resolutions = (const float*)d_in[3];
    float* out = (float*)d_out;

    const int B = in_sizes[0] / F;

    if (B == NB * 64) {
        mdl_pass1_v<32><<<NB, 256>>>(residuals, lambda1, lambda2);
    } else {
        mdl_pass1_s<<<NB, 256>>>(residuals, lambda1, lambda2, (B + NB - 1) / NB);
    }
    mdl_pass2a<<<F, 256>>>(resolutions, B);
    mdl_pass2b<<<1, 256>>>(out);
}

// round 14
// speedup vs baseline: 1.0693x; 1.0693x over previous
#include <cuda_runtime.h>
#include <math.h>

#define F 256
#define NB 512             // partial slots: 512 chunks x 128 rows = B

// Stage-1 partials, transposed: [F][NB] float4 = 2 MB
__device__ float4 g_part[F * NB];
__device__ double g_bits[F];

__device__ __forceinline__ float fast_lg2(float a) {
    float r; asm("lg2.approx.f32 %0, %1;" : "=f"(r) : "f"(a)); return r;
}
__device__ __forceinline__ float fast_ex2(float a) {
    float r; asm("ex2.approx.f32 %0, %1;" : "=f"(r) : "f"(a)); return r;
}

// grid = NB*4 CTAs x 128 threads.
//   chunk = bid >> 2           (row chunk: 128 rows)
//   fq    = bid & 3            (feature quarter: 64 features)
//   f     = fq*64 + (tid & 63)
//   par   = tid >> 6           (row parity: rows 2r+par, r=0..63)
// Same warp supply and per-thread trip count (64) as the best pass1 (R11),
// but partials shrink to 2 MB via a cheap smem parity-combine.
template<int ITER>
__global__ void __launch_bounds__(128) mdl_pass1(
    const float* __restrict__ res,
    const float* __restrict__ lambda1,
    const float* __restrict__ lambda2,
    int iter_rt)
{
    const int chunk = blockIdx.x >> 2;
    const int fl    = threadIdx.x & 63;
    const int f     = ((blockIdx.x & 3) << 6) + fl;
    const int par   = threadIdx.x >> 6;

    const float l1 = lambda1[f];
    const float l2 = lambda2[f];
    // clamp lambdas away from 0 (tiny case flows through the same path)
    float lamP = (fabsf(l1) < 1e-8f) ? 1e-8f : l1;
    float lamN = 2.0f - l2;
    if (fabsf(lamN) < 1e-8f) lamN = 1e-8f;
    const float rlamP  =  1.0f / lamP;
    const float nrlamN = -1.0f / lamN;
    // single-interval safety: safe == (loB < x <= hiB); bad-lambda flags folded in
    const float hiB = (fabsf(l1) <= 1.9f) ? 1000.0f : -0.0f;
    const float loB = (fabsf(l2) <= 1.9f) ? -0.99f  :  0.0f;

    const int iters = (ITER > 0) ? ITER : iter_rt;
    const float* p = res + ((size_t)chunk * 2 * iters + par) * F + f;

    float cnt = 0.0f, sy = 0.0f, sy2 = 0.0f, slj2 = 0.0f;

#pragma unroll 8
    for (int r = 0; r < iters; ++r) {
        const float x = __ldcs(p + r * (2 * F));     // LDG [base+imm]
        const bool pos = (x >= 0.0f);

        // pos clip at 1000 dropped (those elements are masked -> exact);
        // neg clamp at -0.989 kept (affects the safe band (-0.99,-0.989]).
        const float a  = 1.0f + fabsf(fmaxf(x, -0.989f));
        const float t2 = fast_lg2(a);                // log2(1+|x|clip)
        const float lam = pos ? lamP : lamN;
        const float u2  = lam * t2;
        const float ee  = fast_ex2(u2);
        const float rl  = pos ? rlamP : nrlamN;      // sign folded in
        const float y   = fmaf(ee, rl, -rl);         // (2^u2 - 1) * rl

        const bool safe = (x > loB) && (x <= hiB);
        if (safe) {
            cnt  += 1.0f;
            sy   += y;
            sy2   = fmaf(y, y, sy2);
            slj2 += (u2 - t2);                       // log_jac / ln2
        }
    }

    // combine row parities through smem, then one STG.128 per feature
    __shared__ float4 s_acc[2][64];
    s_acc[par][fl] = make_float4(cnt, sy, sy2, slj2);
    __syncthreads();
    if (par == 0) {
        const float4 a = s_acc[0][fl];
        const float4 b = s_acc[1][fl];
        g_part[f * NB + chunk] =
            make_float4(a.x + b.x, a.y + b.y, a.z + b.z, a.w + b.w);
    }
}

// 128 blocks x 256 threads. Block j owns features 2j (warps 0-3) and 2j+1
// (warps 4-7). Each warp reduces a quarter (128) of the NB float4 entries
// (one LDG.128 per entry); smem combine; one thread per feature finishes the
// double-precision bit math.
__global__ __launch_bounds__(256) void mdl_pass2a(
    const float* __restrict__ resolutions, int B)
{
    const int w    = threadIdx.x >> 5;       // 0..7
    const int lane = threadIdx.x & 31;
    const int gf   = blockIdx.x * 2 + (w >> 2);
    const int wq   = w & 3;                  // quarter index

    const float4* b0 = g_part + (size_t)gf * NB;
    const int bbeg = wq * (NB / 4);
    const int bend = bbeg + (NB / 4);

    double cnt = 0.0, sy = 0.0, sy2 = 0.0, slj = 0.0;
#pragma unroll 4
    for (int b = bbeg + lane; b < bend; b += 32) {
        const float4 v = b0[b];
        cnt += (double)v.x;
        sy  += (double)v.y;
        sy2 += (double)v.z;
        slj += (double)v.w;
    }
#pragma unroll
    for (int o = 16; o > 0; o >>= 1) {
        cnt += __shfl_down_sync(0xffffffffu, cnt, o);
        sy  += __shfl_down_sync(0xffffffffu, sy,  o);
        sy2 += __shfl_down_sync(0xffffffffu, sy2, o);
        slj += __shfl_down_sync(0xffffffffu, slj, o);
    }

    __shared__ double sh[8][4];
    if (lane == 0) { sh[w][0] = cnt; sh[w][1] = sy; sh[w][2] = sy2; sh[w][3] = slj; }
    __syncthreads();

    if ((threadIdx.x & 127) == 0) {          // thread 0 and thread 128
        const int wb = (w >> 2) * 4;
        cnt = sh[wb][0] + sh[wb+1][0] + sh[wb+2][0] + sh[wb+3][0];
        sy  = sh[wb][1] + sh[wb+1][1] + sh[wb+2][1] + sh[wb+3][1];
        sy2 = sh[wb][2] + sh[wb+1][2] + sh[wb+2][2] + sh[wb+3][2];
        slj = sh[wb][3] + sh[wb+1][3] + sh[wb+2][3] + sh[wb+3][3];

        const double LN2 = 0.6931471805599453;
        const double LOG2_2PIE = 2.0470955851806783;

        const double Bd    = (double)B;
        const double nf    = cnt;
        const double nexc  = Bd - nf;
        const double denom = fmax(nf, 1.0);
        const double mean  = sy / denom;
        double var = (sy2 - 2.0 * mean * sy + mean * mean * nf) / denom;
        var = fmax(var, 1e-12);

        const double diff_bits = (nf > 1.0) ? nf * (LOG2_2PIE + 0.5 * log2(var)) : 0.0;
        const double jac_bits  = slj;        // accumulated in log2 units
        const double rres      = (double)resolutions[gf];
        const double exc_bits  = (nexc > 0.0) ? nexc * (-log2(rres)) : 0.0;
        const double log_binom = lgamma(Bd + 1.0) - lgamma(nexc + 1.0)
                               - lgamma(Bd - nexc + 1.0);
        const double part_bits = (nexc > 0.0 && nexc < Bd) ? (log_binom / LN2) : 0.0;
        const double lambda_bits = 2.0 * (log(100.0) / LN2);

        g_bits[gf] = diff_bits + jac_bits + exc_bits + part_bits + lambda_bits;
    }
}

__global__ __launch_bounds__(256) void mdl_pass2b(float* __restrict__ out)
{
    const int f = threadIdx.x;
    __shared__ double sh[F];
    sh[f] = g_bits[f];
    __syncthreads();
#pragma unroll
    for (int s = 128; s > 0; s >>= 1) {
        if (f < s) sh[f] += sh[f + s];
        __syncthreads();
    }
    if (f == 0) out[0] = (float)sh[0];
}

extern "C" void kernel_launch(void* const* d_in, const int* in_sizes, int n_in,
                              void* d_out, int out_size)
{
    const float* residuals   = (const float*)d_in[0];
    const float* lambda1     = (const float*)d_in[1];
    const float* lambda2     = (const float*)d_in[2];
    const float* resolutions = (const float*)d_in[3];
    float* out = (float*)d_out;

    const int B = in_sizes[0] / F;

    if (B == NB * 128) {
        mdl_pass1<64><<<NB * 4, 128>>>(residuals, lambda1, lambda2, 64);
    } else {
        const int iters = (B / NB) / 2;      // assumes B % (2*NB) == 0
        mdl_pass1<0><<<NB * 4, 128>>>(residuals, lambda1, lambda2, iters);
    }
    mdl_pass2a<<<F / 2, 256>>>(resolutions, B);
    mdl_pass2b<<<1, 256>>>(out);
}